// round 6
// baseline (speedup 1.0000x reference)
#include <cuda_runtime.h>
#include <cfloat>

// Problem shape (fixed by reference): point_cloud [32, 262144, 3] fp32
static constexpr int NB        = 32;
static constexpr int Q_PER_B   = 262144 * 3 / 4;   // 196608 float4 per batch
static constexpr int THREADS   = 256;

// Work items: 32 per batch, 6144 float4 each (6144 = 8 * 3 * 256, and % 3 == 0)
static constexpr int ITEMS_PER_B = 32;
static constexpr int N_ITEMS     = NB * ITEMS_PER_B;     // 1024
static constexpr int ITEM_Q      = Q_PER_B / ITEMS_PER_B; // 6144 float4
static constexpr int KO_ITERS    = ITEM_Q / (3 * THREADS); // 8

// 444 = 3 * 148: all blocks resident in wave 1 (occupancy >= 4 guaranteed by
// launch bounds, 444 < 4*148 slots under any placement) -> grid barrier is safe.
static constexpr int NBLOCKS   = 444;

// Persistent state. ALL zero-initialized; the last block resets everything to
// zero at the end of each launch -> graph-replay safe, no init kernel.
// g_state: [0]=phase1 work counter, [1]=barrier1, [2]=phase2 work counter, [3]=barrier2
__device__ unsigned g_state[4];
// Per-(batch,coord) extrema. min stored as max of ~f2ord(v), max as max of
// f2ord(v): both monotone, both have sentinel 0 (finite floats encode to
// (0, 0xFFFFFFFF) exclusive), so zero-init is the identity.
__device__ unsigned g_mn[NB * 3];
__device__ unsigned g_mx[NB * 3];

__device__ __forceinline__ unsigned f2ord(float f) {
    unsigned u = __float_as_uint(f);
    return (u & 0x80000000u) ? ~u : (u | 0x80000000u);
}
__device__ __forceinline__ float ord2f(unsigned k) {
    return __uint_as_float((k & 0x80000000u) ? (k ^ 0x80000000u) : ~k);
}

// float4 at index q has components ((q)%3,(q+1)%3,(q+2)%3,(q)%3). All item
// bases are multiples of 3 and the stride THREADS=256 ≡ 1 (mod 3), so with
// r = tid%3 the float4 at sub-iter u has leading component (r+u)%3.

__global__ void __launch_bounds__(THREADS, 4)
fused_voxel_kernel(const float4* __restrict__ p, float4* __restrict__ out) {
    const int tid = threadIdx.x;
    const int r = tid % 3;
    __shared__ unsigned s_item;

    // ───────────── Phase 1: per-batch per-coord min/max (dynamic queue) ─────
    for (;;) {
        __syncthreads();                       // protect s_item reuse
        if (tid == 0) s_item = atomicAdd(&g_state[0], 1u);
        __syncthreads();
        const unsigned item = s_item;
        if (item >= N_ITEMS) break;

        const int b = item >> 5;               // / ITEMS_PER_B
        const int c = item & 31;
        const float4* pb = p + (size_t)b * Q_PER_B + (size_t)c * ITEM_Q;

        // A[s] accumulates component (r+s)%3
        float mnA0 =  FLT_MAX, mnA1 =  FLT_MAX, mnA2 =  FLT_MAX;
        float mxA0 = -FLT_MAX, mxA1 = -FLT_MAX, mxA2 = -FLT_MAX;

        #pragma unroll 2
        for (int ko = 0; ko < KO_ITERS; ko++) {
            const float4 a = pb[(ko * 3 + 0) * THREADS + tid];   // coalesced, default policy (fill L2)
            const float4 d = pb[(ko * 3 + 1) * THREADS + tid];
            const float4 e = pb[(ko * 3 + 2) * THREADS + tid];
            // u=0: comps (A0,A1,A2,A0)
            mnA0 = fminf(mnA0, fminf(a.x, a.w)); mxA0 = fmaxf(mxA0, fmaxf(a.x, a.w));
            mnA1 = fminf(mnA1, a.y);             mxA1 = fmaxf(mxA1, a.y);
            mnA2 = fminf(mnA2, a.z);             mxA2 = fmaxf(mxA2, a.z);
            // u=1: comps (A1,A2,A0,A1)
            mnA1 = fminf(mnA1, fminf(d.x, d.w)); mxA1 = fmaxf(mxA1, fmaxf(d.x, d.w));
            mnA2 = fminf(mnA2, d.y);             mxA2 = fmaxf(mxA2, d.y);
            mnA0 = fminf(mnA0, d.z);             mxA0 = fmaxf(mxA0, d.z);
            // u=2: comps (A2,A0,A1,A2)
            mnA2 = fminf(mnA2, fminf(e.x, e.w)); mxA2 = fmaxf(mxA2, fmaxf(e.x, e.w));
            mnA0 = fminf(mnA0, e.y);             mxA0 = fmaxf(mxA0, e.y);
            mnA1 = fminf(mnA1, e.z);             mxA1 = fmaxf(mxA1, e.z);
        }

        // Un-rotate: comp k lives in slot (k - r + 3) % 3
        float mn0, mn1, mn2, mx0, mx1, mx2;
        if (r == 0)      { mn0 = mnA0; mn1 = mnA1; mn2 = mnA2; mx0 = mxA0; mx1 = mxA1; mx2 = mxA2; }
        else if (r == 1) { mn0 = mnA2; mn1 = mnA0; mn2 = mnA1; mx0 = mxA2; mx1 = mxA0; mx2 = mxA1; }
        else             { mn0 = mnA1; mn1 = mnA2; mn2 = mnA0; mx0 = mxA1; mx1 = mxA2; mx2 = mxA0; }

        // Warp reduce, then warp leaders fire no-return atomics (RED.MAX)
        #pragma unroll
        for (int off = 16; off > 0; off >>= 1) {
            mn0 = fminf(mn0, __shfl_xor_sync(0xFFFFFFFFu, mn0, off));
            mn1 = fminf(mn1, __shfl_xor_sync(0xFFFFFFFFu, mn1, off));
            mn2 = fminf(mn2, __shfl_xor_sync(0xFFFFFFFFu, mn2, off));
            mx0 = fmaxf(mx0, __shfl_xor_sync(0xFFFFFFFFu, mx0, off));
            mx1 = fmaxf(mx1, __shfl_xor_sync(0xFFFFFFFFu, mx1, off));
            mx2 = fmaxf(mx2, __shfl_xor_sync(0xFFFFFFFFu, mx2, off));
        }
        if ((tid & 31) == 0) {
            atomicMax(&g_mn[b * 3 + 0], ~f2ord(mn0));
            atomicMax(&g_mn[b * 3 + 1], ~f2ord(mn1));
            atomicMax(&g_mn[b * 3 + 2], ~f2ord(mn2));
            atomicMax(&g_mx[b * 3 + 0],  f2ord(mx0));
            atomicMax(&g_mx[b * 3 + 1],  f2ord(mx1));
            atomicMax(&g_mx[b * 3 + 2],  f2ord(mx2));
        }
    }

    // ───────────── Grid barrier (all 444 blocks resident -> safe) ───────────
    __threadfence();
    if (tid == 0) {
        atomicAdd(&g_state[1], 1u);
        while (__ldcg((const unsigned*)&g_state[1]) < (unsigned)NBLOCKS) __nanosleep(128);
        __threadfence();
    }
    __syncthreads();

    // ───────────── Phase 2: voxels = floor((p - min) / bin_width) ───────────
    for (;;) {
        __syncthreads();
        if (tid == 0) s_item = atomicAdd(&g_state[2], 1u);
        __syncthreads();
        const unsigned item = s_item;
        if (item >= N_ITEMS) break;

        const int b = item >> 5;
        const int c = item & 31;
        const size_t base = (size_t)b * Q_PER_B + (size_t)c * ITEM_Q;
        const float4* pb = p + base;
        float4* ob = out + base;

        // Finalized extrema (L2 reads; uniform address -> broadcast)
        float mnc[3], invc[3];
        #pragma unroll
        for (int k = 0; k < 3; k++) {
            const float mnv = ord2f(~__ldcg(&g_mn[b * 3 + k]));
            const float mxv = ord2f( __ldcg(&g_mx[b * 3 + k]));
            mnc[k]  = mnv;
            invc[k] = 1.0f / ((mxv - mnv) / 40.0f);   // same RN /40 as reference
        }
        const float mn_0 = mnc[r], mn_1 = mnc[(r + 1) % 3], mn_2 = mnc[(r + 2) % 3];
        const float iv_0 = invc[r], iv_1 = invc[(r + 1) % 3], iv_2 = invc[(r + 2) % 3];

        #pragma unroll 2
        for (int ko = 0; ko < KO_ITERS; ko++) {
            const float4 a = __ldcs(&pb[(ko * 3 + 0) * THREADS + tid]);  // L2 hit expected
            const float4 d = __ldcs(&pb[(ko * 3 + 1) * THREADS + tid]);
            const float4 e = __ldcs(&pb[(ko * 3 + 2) * THREADS + tid]);

            float4 ra, rd, re;
            // u=0: comps (0,1,2,0) after rotation
            ra.x = floorf((a.x - mn_0) * iv_0);
            ra.y = floorf((a.y - mn_1) * iv_1);
            ra.z = floorf((a.z - mn_2) * iv_2);
            ra.w = floorf((a.w - mn_0) * iv_0);
            // u=1: comps (1,2,0,1)
            rd.x = floorf((d.x - mn_1) * iv_1);
            rd.y = floorf((d.y - mn_2) * iv_2);
            rd.z = floorf((d.z - mn_0) * iv_0);
            rd.w = floorf((d.w - mn_1) * iv_1);
            // u=2: comps (2,0,1,2)
            re.x = floorf((e.x - mn_2) * iv_2);
            re.y = floorf((e.y - mn_0) * iv_0);
            re.z = floorf((e.z - mn_1) * iv_1);
            re.w = floorf((e.w - mn_2) * iv_2);

            __stcs(&ob[(ko * 3 + 0) * THREADS + tid], ra);
            __stcs(&ob[(ko * 3 + 1) * THREADS + tid], rd);
            __stcs(&ob[(ko * 3 + 2) * THREADS + tid], re);
        }
    }

    // ───────────── Last block resets all persistent state for next replay ───
    __syncthreads();
    if (tid == 0) {
        const unsigned v = atomicAdd(&g_state[3], 1u);
        s_item = (v == (unsigned)(NBLOCKS - 1)) ? 1u : 0u;   // last arriver
    }
    __syncthreads();
    if (s_item) {
        if (tid < NB * 3) { g_mn[tid] = 0u; g_mx[tid] = 0u; }
        if (tid < 4) g_state[tid] = 0u;
    }
}

extern "C" void kernel_launch(void* const* d_in, const int* in_sizes, int n_in,
                              void* d_out, int out_size) {
    const float4* p = (const float4*)d_in[0];
    float4* o = (float4*)d_out;
    fused_voxel_kernel<<<NBLOCKS, THREADS>>>(p, o);
}

// round 7
// speedup vs baseline: 1.4043x; 1.4043x over previous
#include <cuda_runtime.h>
#include <cfloat>

// Problem shape (fixed by reference): point_cloud [32, 262144, 3] fp32
static constexpr int NB       = 32;
static constexpr int NPTS     = 262144;
static constexpr int F_PER_B  = NPTS * 3;        // 786432 floats per batch
static constexpr int Q_PER_B  = F_PER_B / 4;     // 196608 float4 per batch

static constexpr int THREADS  = 256;
static constexpr int BLOCKS1  = 32;              // pass-1 blocks/batch (== warp size for prologue reduce)
static constexpr int CHUNK1   = Q_PER_B / BLOCKS1;   // 6144 float4/block -> 24 loads/thread
static constexpr int BLOCKS2  = 64;              // pass-2 blocks/batch
static constexpr int CHUNK2   = Q_PER_B / BLOCKS2;   // 3072 float4/block -> 12 loads/thread

// Per-(batch, quantity, block) partials; every slot written unconditionally
// each launch -> no init kernel, no atomics, graph-replay safe.
// Quantity: 0..2 = min(x,y,z), 3..5 = max(x,y,z).
__device__ float g_part[NB][6][BLOCKS1];

// Component bookkeeping: float4 at index idx has components
// ((idx)%3, (idx+1)%3, (idx+2)%3, (idx)%3). Block bases are multiples of 3
// and the per-iteration stride is THREADS=256 ≡ 1 (mod 3), so with
// r = tid%3 the float4 loaded at unrolled sub-iter u has leading component
// (r+u)%3. All selection is static after pre-rotating constants by r.

// ───────────────── Pass 1: per-batch per-coord min/max partials ─────────────
__global__ void __launch_bounds__(THREADS)
minmax_kernel(const float4* __restrict__ p) {
    const int b = blockIdx.y;
    const float4* pb = p + (size_t)b * Q_PER_B + blockIdx.x * CHUNK1;
    const int tid = threadIdx.x;
    const int r = tid % 3;

    // A[s] accumulates component (r+s)%3
    float mnA0 =  FLT_MAX, mnA1 =  FLT_MAX, mnA2 =  FLT_MAX;
    float mxA0 = -FLT_MAX, mxA1 = -FLT_MAX, mxA2 = -FLT_MAX;

    #pragma unroll 2
    for (int ko = 0; ko < CHUNK1 / (3 * THREADS); ko++) {   // 8 outer iters
        const float4 a = pb[(ko * 3 + 0) * THREADS + tid];  // coalesced, default policy (fills L2)
        const float4 d = pb[(ko * 3 + 1) * THREADS + tid];
        const float4 c = pb[(ko * 3 + 2) * THREADS + tid];
        // u=0: comps (A0,A1,A2,A0)
        mnA0 = fminf(mnA0, fminf(a.x, a.w)); mxA0 = fmaxf(mxA0, fmaxf(a.x, a.w));
        mnA1 = fminf(mnA1, a.y);             mxA1 = fmaxf(mxA1, a.y);
        mnA2 = fminf(mnA2, a.z);             mxA2 = fmaxf(mxA2, a.z);
        // u=1: comps (A1,A2,A0,A1)
        mnA1 = fminf(mnA1, fminf(d.x, d.w)); mxA1 = fmaxf(mxA1, fmaxf(d.x, d.w));
        mnA2 = fminf(mnA2, d.y);             mxA2 = fmaxf(mxA2, d.y);
        mnA0 = fminf(mnA0, d.z);             mxA0 = fmaxf(mxA0, d.z);
        // u=2: comps (A2,A0,A1,A2)
        mnA2 = fminf(mnA2, fminf(c.x, c.w)); mxA2 = fmaxf(mxA2, fmaxf(c.x, c.w));
        mnA0 = fminf(mnA0, c.y);             mxA0 = fmaxf(mxA0, c.y);
        mnA1 = fminf(mnA1, c.z);             mxA1 = fmaxf(mxA1, c.z);
    }

    // Un-rotate: comp c lives in slot (c - r + 3) % 3
    float mn0, mn1, mn2, mx0, mx1, mx2;
    if (r == 0)      { mn0 = mnA0; mn1 = mnA1; mn2 = mnA2; mx0 = mxA0; mx1 = mxA1; mx2 = mxA2; }
    else if (r == 1) { mn0 = mnA2; mn1 = mnA0; mn2 = mnA1; mx0 = mxA2; mx1 = mxA0; mx2 = mxA1; }
    else             { mn0 = mnA1; mn1 = mnA2; mn2 = mnA0; mx0 = mxA1; mx1 = mxA2; mx2 = mxA0; }

    // Warp reduction
    #pragma unroll
    for (int off = 16; off > 0; off >>= 1) {
        mn0 = fminf(mn0, __shfl_xor_sync(0xFFFFFFFFu, mn0, off));
        mn1 = fminf(mn1, __shfl_xor_sync(0xFFFFFFFFu, mn1, off));
        mn2 = fminf(mn2, __shfl_xor_sync(0xFFFFFFFFu, mn2, off));
        mx0 = fmaxf(mx0, __shfl_xor_sync(0xFFFFFFFFu, mx0, off));
        mx1 = fmaxf(mx1, __shfl_xor_sync(0xFFFFFFFFu, mx1, off));
        mx2 = fmaxf(mx2, __shfl_xor_sync(0xFFFFFFFFu, mx2, off));
    }

    __shared__ float s[6][THREADS / 32];
    const int w = tid >> 5, lane = tid & 31;
    if (lane == 0) {
        s[0][w] = mn0; s[1][w] = mn1; s[2][w] = mn2;
        s[3][w] = mx0; s[4][w] = mx1; s[5][w] = mx2;
    }
    __syncthreads();

    if (tid < 6) {
        float v = s[tid][0];
        if (tid < 3) {
            #pragma unroll
            for (int k = 1; k < THREADS / 32; k++) v = fminf(v, s[tid][k]);
        } else {
            #pragma unroll
            for (int k = 1; k < THREADS / 32; k++) v = fmaxf(v, s[tid][k]);
        }
        g_part[b][tid][blockIdx.x] = v;
    }
}

// ───────────────── Pass 2: voxels = floor((p - min) / bin_width) ────────────
__global__ void __launch_bounds__(THREADS)
voxel_kernel(const float4* __restrict__ p, float4* __restrict__ out) {
    const int b = blockIdx.y;
    const int tid = threadIdx.x;

    // Prologue: warps 0..5 each reduce the 32 per-block partials for one quantity.
    __shared__ float cst[6];
    {
        const int w = tid >> 5, lane = tid & 31;
        if (w < 6) {
            float v = g_part[b][w][lane];
            if (w < 3) {
                #pragma unroll
                for (int off = 16; off > 0; off >>= 1)
                    v = fminf(v, __shfl_xor_sync(0xFFFFFFFFu, v, off));
            } else {
                #pragma unroll
                for (int off = 16; off > 0; off >>= 1)
                    v = fmaxf(v, __shfl_xor_sync(0xFFFFFFFFu, v, off));
            }
            if (lane == 0) cst[w] = v;
        }
    }
    __syncthreads();

    // Per-component constants, same RN division by 40 as reference, then
    // reciprocal-multiply per point (rel err << 1e-3 threshold).
    const float mnc[3]  = { cst[0], cst[1], cst[2] };
    const float invc[3] = { 1.0f / ((cst[3] - cst[0]) / 40.0f),
                            1.0f / ((cst[4] - cst[1]) / 40.0f),
                            1.0f / ((cst[5] - cst[2]) / 40.0f) };

    // Pre-rotate by r = tid % 3: slot s covers component (r+s)%3.
    const int r = tid % 3;
    const float mn_0 = mnc[r], mn_1 = mnc[(r + 1) % 3], mn_2 = mnc[(r + 2) % 3];
    const float iv_0 = invc[r], iv_1 = invc[(r + 1) % 3], iv_2 = invc[(r + 2) % 3];

    const size_t base = (size_t)b * Q_PER_B + blockIdx.x * CHUNK2;
    const float4* pb = p + base;
    float4* ob = out + base;

    #pragma unroll 2
    for (int ko = 0; ko < CHUNK2 / (3 * THREADS); ko++) {   // 4 outer iters
        const float4 a = __ldcs(&pb[(ko * 3 + 0) * THREADS + tid]);  // L2 hit expected (pass-1 residue)
        const float4 d = __ldcs(&pb[(ko * 3 + 1) * THREADS + tid]);
        const float4 c = __ldcs(&pb[(ko * 3 + 2) * THREADS + tid]);

        float4 ra, rd, rc;
        // u=0: comps (0,1,2,0) after rotation
        ra.x = floorf((a.x - mn_0) * iv_0);
        ra.y = floorf((a.y - mn_1) * iv_1);
        ra.z = floorf((a.z - mn_2) * iv_2);
        ra.w = floorf((a.w - mn_0) * iv_0);
        // u=1: comps (1,2,0,1)
        rd.x = floorf((d.x - mn_1) * iv_1);
        rd.y = floorf((d.y - mn_2) * iv_2);
        rd.z = floorf((d.z - mn_0) * iv_0);
        rd.w = floorf((d.w - mn_1) * iv_1);
        // u=2: comps (2,0,1,2)
        rc.x = floorf((c.x - mn_2) * iv_2);
        rc.y = floorf((c.y - mn_0) * iv_0);
        rc.z = floorf((c.z - mn_1) * iv_1);
        rc.w = floorf((c.w - mn_2) * iv_2);

        // Write-through: don't hold dirty output lines in L2 -> input's
        // pass-1 footprint stays resident -> pass-2 reads keep hitting L2.
        __stwt(&ob[(ko * 3 + 0) * THREADS + tid], ra);
        __stwt(&ob[(ko * 3 + 1) * THREADS + tid], rd);
        __stwt(&ob[(ko * 3 + 2) * THREADS + tid], rc);
    }
}

extern "C" void kernel_launch(void* const* d_in, const int* in_sizes, int n_in,
                              void* d_out, int out_size) {
    const float4* p = (const float4*)d_in[0];
    float4* o = (float4*)d_out;

    minmax_kernel<<<dim3(BLOCKS1, NB), THREADS>>>(p);
    voxel_kernel<<<dim3(BLOCKS2, NB), THREADS>>>(p, o);
}

// round 8
// speedup vs baseline: 1.5306x; 1.0900x over previous
#include <cuda_runtime.h>
#include <cfloat>

// Problem shape (fixed by reference): point_cloud [32, 262144, 3] fp32
static constexpr int NB       = 32;
static constexpr int NPTS     = 262144;
static constexpr int F_PER_B  = NPTS * 3;        // 786432 floats per batch
static constexpr int Q_PER_B  = F_PER_B / 4;     // 196608 float4 per batch

static constexpr int THREADS  = 256;
static constexpr int BLOCKS1  = 32;              // pass-1 blocks/batch (== warp size for prologue reduce)
static constexpr int CHUNK1   = Q_PER_B / BLOCKS1;   // 6144 float4/block
static constexpr int ITER1    = CHUNK1 / (3 * THREADS); // 8
static constexpr int BLOCKS2  = 64;              // pass-2 blocks/batch
static constexpr int CHUNK2   = Q_PER_B / BLOCKS2;   // 3072 float4/block
static constexpr int ITER2    = CHUNK2 / (3 * THREADS); // 4

// Per-(batch, quantity, block) partials; every slot written unconditionally
// each launch -> no init kernel, no atomics, graph-replay safe.
// Quantity: 0..2 = min(x,y,z), 3..5 = max(x,y,z).
__device__ float g_part[NB][6][BLOCKS1];

// Component bookkeeping: float4 at index idx has components
// ((idx)%3, (idx+1)%3, (idx+2)%3, (idx)%3). Block bases are multiples of 3
// and the per-iteration stride is THREADS=256 ≡ 1 (mod 3), so with
// r = tid%3 the float4 loaded at unrolled sub-iter u has leading component
// (r+u)%3. All selection is static after pre-rotating constants by r.

// ───────────────── Pass 1: per-batch per-coord min/max partials ─────────────
__global__ void __launch_bounds__(THREADS)
minmax_kernel(const float4* __restrict__ p) {
    const int b = blockIdx.y;
    const float4* pb = p + (size_t)b * Q_PER_B + blockIdx.x * CHUNK1;
    const int tid = threadIdx.x;
    const int r = tid % 3;

    // A[s] accumulates component (r+s)%3
    float mnA0 =  FLT_MAX, mnA1 =  FLT_MAX, mnA2 =  FLT_MAX;
    float mxA0 = -FLT_MAX, mxA1 = -FLT_MAX, mxA2 = -FLT_MAX;

    #pragma unroll 4
    for (int ko = 0; ko < ITER1; ko++) {
        const float4 a = pb[(ko * 3 + 0) * THREADS + tid];  // coalesced, default policy (fills L2)
        const float4 d = pb[(ko * 3 + 1) * THREADS + tid];
        const float4 c = pb[(ko * 3 + 2) * THREADS + tid];
        // u=0: comps (A0,A1,A2,A0)
        mnA0 = fminf(mnA0, fminf(a.x, a.w)); mxA0 = fmaxf(mxA0, fmaxf(a.x, a.w));
        mnA1 = fminf(mnA1, a.y);             mxA1 = fmaxf(mxA1, a.y);
        mnA2 = fminf(mnA2, a.z);             mxA2 = fmaxf(mxA2, a.z);
        // u=1: comps (A1,A2,A0,A1)
        mnA1 = fminf(mnA1, fminf(d.x, d.w)); mxA1 = fmaxf(mxA1, fmaxf(d.x, d.w));
        mnA2 = fminf(mnA2, d.y);             mxA2 = fmaxf(mxA2, d.y);
        mnA0 = fminf(mnA0, d.z);             mxA0 = fmaxf(mxA0, d.z);
        // u=2: comps (A2,A0,A1,A2)
        mnA2 = fminf(mnA2, fminf(c.x, c.w)); mxA2 = fmaxf(mxA2, fmaxf(c.x, c.w));
        mnA0 = fminf(mnA0, c.y);             mxA0 = fmaxf(mxA0, c.y);
        mnA1 = fminf(mnA1, c.z);             mxA1 = fmaxf(mxA1, c.z);
    }

    // Un-rotate: comp c lives in slot (c - r + 3) % 3
    float mn0, mn1, mn2, mx0, mx1, mx2;
    if (r == 0)      { mn0 = mnA0; mn1 = mnA1; mn2 = mnA2; mx0 = mxA0; mx1 = mxA1; mx2 = mxA2; }
    else if (r == 1) { mn0 = mnA2; mn1 = mnA0; mn2 = mnA1; mx0 = mxA2; mx1 = mxA0; mx2 = mxA1; }
    else             { mn0 = mnA1; mn1 = mnA2; mn2 = mnA0; mx0 = mxA1; mx1 = mxA2; mx2 = mxA0; }

    // Warp reduction
    #pragma unroll
    for (int off = 16; off > 0; off >>= 1) {
        mn0 = fminf(mn0, __shfl_xor_sync(0xFFFFFFFFu, mn0, off));
        mn1 = fminf(mn1, __shfl_xor_sync(0xFFFFFFFFu, mn1, off));
        mn2 = fminf(mn2, __shfl_xor_sync(0xFFFFFFFFu, mn2, off));
        mx0 = fmaxf(mx0, __shfl_xor_sync(0xFFFFFFFFu, mx0, off));
        mx1 = fmaxf(mx1, __shfl_xor_sync(0xFFFFFFFFu, mx1, off));
        mx2 = fmaxf(mx2, __shfl_xor_sync(0xFFFFFFFFu, mx2, off));
    }

    __shared__ float s[6][THREADS / 32];
    const int w = tid >> 5, lane = tid & 31;
    if (lane == 0) {
        s[0][w] = mn0; s[1][w] = mn1; s[2][w] = mn2;
        s[3][w] = mx0; s[4][w] = mx1; s[5][w] = mx2;
    }
    __syncthreads();

    if (tid < 6) {
        float v = s[tid][0];
        if (tid < 3) {
            #pragma unroll
            for (int k = 1; k < THREADS / 32; k++) v = fminf(v, s[tid][k]);
        } else {
            #pragma unroll
            for (int k = 1; k < THREADS / 32; k++) v = fmaxf(v, s[tid][k]);
        }
        g_part[b][tid][blockIdx.x] = v;
    }
}

// ───────────────── Pass 2: voxels = floor((p - min) / bin_width) ────────────
// Double-buffered: prefetch iteration ko+1's three float4 while computing and
// storing iteration ko -> ~6 LDG.128 in flight per thread (vs ~2 before).
__global__ void __launch_bounds__(THREADS, 4)
voxel_kernel(const float4* __restrict__ p, float4* __restrict__ out) {
    const int b = blockIdx.y;
    const int tid = threadIdx.x;

    // Prologue: warps 0..5 each reduce the 32 per-block partials for one quantity.
    __shared__ float cst[6];
    {
        const int w = tid >> 5, lane = tid & 31;
        if (w < 6) {
            float v = g_part[b][w][lane];
            if (w < 3) {
                #pragma unroll
                for (int off = 16; off > 0; off >>= 1)
                    v = fminf(v, __shfl_xor_sync(0xFFFFFFFFu, v, off));
            } else {
                #pragma unroll
                for (int off = 16; off > 0; off >>= 1)
                    v = fmaxf(v, __shfl_xor_sync(0xFFFFFFFFu, v, off));
            }
            if (lane == 0) cst[w] = v;
        }
    }
    __syncthreads();

    // Per-component constants, same RN division by 40 as reference, then
    // reciprocal-multiply per point (rel err << 1e-3 threshold).
    const float mnc[3]  = { cst[0], cst[1], cst[2] };
    const float invc[3] = { 1.0f / ((cst[3] - cst[0]) / 40.0f),
                            1.0f / ((cst[4] - cst[1]) / 40.0f),
                            1.0f / ((cst[5] - cst[2]) / 40.0f) };

    // Pre-rotate by r = tid % 3: slot s covers component (r+s)%3.
    const int r = tid % 3;
    const float mn_0 = mnc[r], mn_1 = mnc[(r + 1) % 3], mn_2 = mnc[(r + 2) % 3];
    const float iv_0 = invc[r], iv_1 = invc[(r + 1) % 3], iv_2 = invc[(r + 2) % 3];

    const size_t base = (size_t)b * Q_PER_B + blockIdx.x * CHUNK2;
    const float4* pb = p + base;
    float4* ob = out + base;

    // Prime the pipeline (iteration 0's loads)
    float4 a = __ldcs(&pb[0 * THREADS + tid]);
    float4 d = __ldcs(&pb[1 * THREADS + tid]);
    float4 c = __ldcs(&pb[2 * THREADS + tid]);

    #pragma unroll
    for (int ko = 0; ko < ITER2; ko++) {
        // Prefetch next iteration before consuming current
        float4 an, dn, cn;
        if (ko + 1 < ITER2) {
            an = __ldcs(&pb[((ko + 1) * 3 + 0) * THREADS + tid]);
            dn = __ldcs(&pb[((ko + 1) * 3 + 1) * THREADS + tid]);
            cn = __ldcs(&pb[((ko + 1) * 3 + 2) * THREADS + tid]);
        }

        float4 ra, rd, rc;
        // u=0: comps (0,1,2,0) after rotation
        ra.x = floorf((a.x - mn_0) * iv_0);
        ra.y = floorf((a.y - mn_1) * iv_1);
        ra.z = floorf((a.z - mn_2) * iv_2);
        ra.w = floorf((a.w - mn_0) * iv_0);
        // u=1: comps (1,2,0,1)
        rd.x = floorf((d.x - mn_1) * iv_1);
        rd.y = floorf((d.y - mn_2) * iv_2);
        rd.z = floorf((d.z - mn_0) * iv_0);
        rd.w = floorf((d.w - mn_1) * iv_1);
        // u=2: comps (2,0,1,2)
        rc.x = floorf((c.x - mn_2) * iv_2);
        rc.y = floorf((c.y - mn_0) * iv_0);
        rc.z = floorf((c.z - mn_1) * iv_1);
        rc.w = floorf((c.w - mn_2) * iv_2);

        __stcs(&ob[(ko * 3 + 0) * THREADS + tid], ra);
        __stcs(&ob[(ko * 3 + 1) * THREADS + tid], rd);
        __stcs(&ob[(ko * 3 + 2) * THREADS + tid], rc);

        a = an; d = dn; c = cn;
    }
}

extern "C" void kernel_launch(void* const* d_in, const int* in_sizes, int n_in,
                              void* d_out, int out_size) {
    const float4* p = (const float4*)d_in[0];
    float4* o = (float4*)d_out;

    minmax_kernel<<<dim3(BLOCKS1, NB), THREADS>>>(p);
    voxel_kernel<<<dim3(BLOCKS2, NB), THREADS>>>(p, o);
}